// round 3
// baseline (speedup 1.0000x reference)
#include <cuda_runtime.h>

#define N_ENTITY 100000
#define DD 128
#define HIDSZ 256
#define N_REL 48
#define NB 8
#define NEDGE 1000000
#define N_POS 1024
#define CAP (1 << 17)
#define ZMAX (N_POS * N_REL)
#define TILE 8

// ---- device scratch (no allocation allowed) ----
__device__ int   g_map[N_ENTITY];            // node id -> canonical position (min pos), else big
__device__ int   g_deg[N_POS * N_REL];       // per (slot, rel) in-degree
__device__ float g_s[N_POS * N_REL * DD];    // raw segment sums (only deg>0 rows valid)
__device__ int4  g_ce[CAP];                  // compacted edges: (src, slot, rel, -)
__device__ int   g_cnt;
__device__ int   g_zlist[ZMAX];              // rows with deg>=2 (need zero + atomic accum)
__device__ int   g_zcnt;

// ---- K0: init small scratch only ----
__global__ void k_init0() {
    int i = blockIdx.x * blockDim.x + threadIdx.x;
    if (i < N_ENTITY) g_map[i] = 0x7fffffff;
    if (i < N_POS * N_REL) g_deg[i] = 0;
    if (i == 0) { g_cnt = 0; g_zcnt = 0; }
}

// ---- K1: scatter entity positions into the map (min pos = canonical) ----
__global__ void k_scatter(const int* __restrict__ ids) {
    int i = blockIdx.x * blockDim.x + threadIdx.x;
    if (i < N_POS) atomicMin(&g_map[ids[i]], i);
}

// ---- K2: scan all edges (4/thread), compact hits, degree + zero-list ----
__global__ void k_filter(const int* __restrict__ ei, const int* __restrict__ et) {
    int t = blockIdx.x * blockDim.x + threadIdx.x;
    if (t * 4 >= NEDGE) return;
    int4 dst4 = reinterpret_cast<const int4*>(ei + NEDGE)[t];
    int ds[4] = {dst4.x, dst4.y, dst4.z, dst4.w};
#pragma unroll
    for (int q = 0; q < 4; ++q) {
        int e = t * 4 + q;
        int slot = g_map[ds[q]];
        if (slot < N_POS) {
            int rel = __ldg(&et[e]);
            int row = slot * N_REL + rel;
            int old = atomicAdd(&g_deg[row], 1);
            if (old == 1) {  // second edge on this row -> it needs zero+atomic path
                int zp = atomicAdd(&g_zcnt, 1);
                if (zp < ZMAX) g_zlist[zp] = row;
            }
            int p = atomicAdd(&g_cnt, 1);
            if (p < CAP) g_ce[p] = make_int4(__ldg(&ei[e]), slot, rel, 0);
        }
    }
}

// ---- K2b: zero only listed rows (deg>=2), one warp per row ----
__global__ void k_zero() {
    int w = (blockIdx.x * blockDim.x + threadIdx.x) >> 5;
    int lane = threadIdx.x & 31;
    int nw = (gridDim.x * blockDim.x) >> 5;
    int n = min(g_zcnt, ZMAX);
    float4 z = make_float4(0.f, 0.f, 0.f, 0.f);
    for (int i = w; i < n; i += nw) {
        int row = g_zlist[i];
        reinterpret_cast<float4*>(g_s + (size_t)row * DD)[lane] = z;
    }
}

// ---- K3: one warp per compacted edge. deg==1: plain store; else atomicAdd ----
__global__ void k_accum(const float* __restrict__ x) {
    int warp = (blockIdx.x * blockDim.x + threadIdx.x) >> 5;
    int lane = threadIdx.x & 31;
    int nwarp = (gridDim.x * blockDim.x) >> 5;
    int cnt = min(g_cnt, CAP);
    for (int i = warp; i < cnt; i += nwarp) {
        int4 ce = g_ce[i];
        int row = ce.y * N_REL + ce.z;
        int dg = g_deg[row];
        float4 xv = reinterpret_cast<const float4*>(x + (long)ce.x * DD)[lane];
        float* sp = &g_s[(size_t)row * DD + lane * 4];
        if (dg == 1) {
            *reinterpret_cast<float4*>(sp) = xv;
        } else {
            atomicAdd(sp + 0, xv.x);
            atomicAdd(sp + 1, xv.y);
            atomicAdd(sp + 2, xv.z);
            atomicAdd(sp + 3, xv.w);
        }
    }
}

// ---- K4: fused per-position pipeline ----
// 512 threads = 4 groups of 128; block handles TILE=8 positions (2 per group).
__global__ __launch_bounds__(512)
void k_final(const float* __restrict__ x, const float* __restrict__ bases,
             const float* __restrict__ comp, const float* __restrict__ root,
             const float* __restrict__ bias,
             const float* __restrict__ w1, const float* __restrict__ b1,
             const float* __restrict__ w2, const float* __restrict__ b2,
             const float* __restrict__ wp, const float* __restrict__ bp,
             const int* __restrict__ ids, float* __restrict__ out) {
    extern __shared__ float sm[];
    float* xs    = sm;                        // 1024
    float* vv    = xs + TILE * DD;            // 8192
    float* compS = vv + TILE * NB * DD;       // 384
    float* normS = compS + N_REL * NB;        // 384
    float* hb    = normS + TILE * N_REL;      // 1024
    float* zb    = hb + TILE * DD;            // 512
    int*  canon  = (int*)(zb + TILE * 64);    // 8 ints

    const int tid = threadIdx.x;
    const int gid = tid >> 7;      // 0..3
    const int d   = tid & 127;
    const int pbase = blockIdx.x * TILE;

    if (tid < TILE) canon[tid] = g_map[ids[pbase + tid]];
    for (int i = tid; i < TILE * DD; i += 512) {
        int p = i >> 7;
        xs[i] = x[(long)ids[pbase + p] * DD + (i & 127)];
    }
    if (tid < N_REL * NB) compS[tid] = comp[tid];
    __syncthreads();
    if (tid < TILE * N_REL) {
        int p = tid / N_REL, r = tid % N_REL;
        int dg = g_deg[canon[p] * N_REL + r];
        normS[tid] = dg > 0 ? 1.0f / (float)dg : 0.0f;
    }
    __syncthreads();

    // phase 2: vv[p][k][d] = sum_{r: deg>0} norm[p][r]*s[canon_p][r][d]*comp[r][k]
#pragma unroll
    for (int p = 0; p < 2; ++p) {
        int pp = gid * 2 + p;
        const float* srow = &g_s[(size_t)canon[pp] * N_REL * DD + d];
        float acc[NB];
#pragma unroll
        for (int k = 0; k < NB; ++k) acc[k] = 0.0f;
        for (int r = 0; r < N_REL; ++r) {
            float nm = normS[pp * N_REL + r];
            if (nm != 0.0f) {
                float sv = srow[r * DD] * nm;
#pragma unroll
                for (int k = 0; k < NB; ++k) acc[k] += sv * compS[r * NB + k];
            }
        }
#pragma unroll
        for (int k = 0; k < NB; ++k) vv[(pp * NB + k) * DD + d] = acc[k];
    }
    __syncthreads();

    // phase 3: rgcn out + residual -> hb (j-unrolled x4, float4 smem reads)
    {
        const int pp0 = gid * 2;
        float acc0 = bias[d], acc1 = acc0;
        const float4* xs0 = reinterpret_cast<const float4*>(xs + pp0 * DD);
        const float4* xs1 = reinterpret_cast<const float4*>(xs + (pp0 + 1) * DD);
#pragma unroll 4
        for (int j4 = 0; j4 < DD / 4; ++j4) {
            float r0 = root[(j4 * 4 + 0) * DD + d];
            float r1 = root[(j4 * 4 + 1) * DD + d];
            float r2 = root[(j4 * 4 + 2) * DD + d];
            float r3 = root[(j4 * 4 + 3) * DD + d];
            float4 a = xs0[j4], b = xs1[j4];
            acc0 += a.x * r0 + a.y * r1 + a.z * r2 + a.w * r3;
            acc1 += b.x * r0 + b.y * r1 + b.z * r2 + b.w * r3;
        }
#pragma unroll 1
        for (int k = 0; k < NB; ++k) {
            const float4* v0 = reinterpret_cast<const float4*>(vv + (pp0 * NB + k) * DD);
            const float4* v1 = reinterpret_cast<const float4*>(vv + ((pp0 + 1) * NB + k) * DD);
            const float* bk = bases + (size_t)k * DD * DD + d;
#pragma unroll 4
            for (int j4 = 0; j4 < DD / 4; ++j4) {
                float b0 = bk[(j4 * 4 + 0) * DD];
                float b1 = bk[(j4 * 4 + 1) * DD];
                float b2 = bk[(j4 * 4 + 2) * DD];
                float b3 = bk[(j4 * 4 + 3) * DD];
                float4 a = v0[j4], c = v1[j4];
                acc0 += a.x * b0 + a.y * b1 + a.z * b2 + a.w * b3;
                acc1 += c.x * b0 + c.y * b1 + c.z * b2 + c.w * b3;
            }
        }
        hb[pp0 * DD + d] = acc0 + xs[pp0 * DD + d];
        hb[(pp0 + 1) * DD + d] = acc1 + xs[(pp0 + 1) * DD + d];
    }
    __syncthreads();

    // phase 5: zb[p][c] = relu(hb[p] @ w1 + b1)   (512 outputs, 1/thread)
    {
        int p = tid >> 6, c = tid & 63;
        float acc = b1[c];
        const float4* h4 = reinterpret_cast<const float4*>(hb + p * DD);
#pragma unroll 4
        for (int j4 = 0; j4 < DD / 4; ++j4) {
            float w0 = w1[(j4 * 4 + 0) * 64 + c];
            float w1v = w1[(j4 * 4 + 1) * 64 + c];
            float w2v = w1[(j4 * 4 + 2) * 64 + c];
            float w3 = w1[(j4 * 4 + 3) * 64 + c];
            float4 h = h4[j4];
            acc += h.x * w0 + h.y * w1v + h.z * w2v + h.w * w3;
        }
        zb[p * 64 + c] = fmaxf(acc, 0.0f);
    }
    __syncthreads();

    // phase 6: hb[p][d] += zb[p] @ w2 + b2   (1024 outputs, 2/thread)
#pragma unroll
    for (int t = 0; t < 2; ++t) {
        int i = t * 512 + tid;
        int p = i >> 7, dd2 = i & 127;
        float acc = b2[dd2] + hb[i];
        const float4* z4 = reinterpret_cast<const float4*>(zb + p * 64);
#pragma unroll 4
        for (int c4 = 0; c4 < 16; ++c4) {
            float w0 = w2[(c4 * 4 + 0) * DD + dd2];
            float w1v = w2[(c4 * 4 + 1) * DD + dd2];
            float w2v = w2[(c4 * 4 + 2) * DD + dd2];
            float w3 = w2[(c4 * 4 + 3) * DD + dd2];
            float4 z = z4[c4];
            acc += z.x * w0 + z.y * w1v + z.z * w2v + z.w * w3;
        }
        __syncthreads();   // all reads of hb done before overwrite? (t=0 writes same idx it read)
        hb[i] = acc;
        __syncthreads();
    }

    // phase 7: out[pos][o] = hb[p] @ wp + bp    (2048 outputs, 4/thread)
    {
        int o = tid & 255, po = tid >> 8;  // po: 0 or 1
#pragma unroll
        for (int pi = 0; pi < 4; ++pi) {
            int p = pi * 2 + po;
            float acc = bp[o];
            const float4* h4 = reinterpret_cast<const float4*>(hb + p * DD);
#pragma unroll 4
            for (int j4 = 0; j4 < DD / 4; ++j4) {
                float w0 = wp[(size_t)(j4 * 4 + 0) * HIDSZ + o];
                float w1v = wp[(size_t)(j4 * 4 + 1) * HIDSZ + o];
                float w2v = wp[(size_t)(j4 * 4 + 2) * HIDSZ + o];
                float w3 = wp[(size_t)(j4 * 4 + 3) * HIDSZ + o];
                float4 h = h4[j4];
                acc += h.x * w0 + h.y * w1v + h.z * w2v + h.w * w3;
            }
            out[((long)(pbase + p)) * HIDSZ + o] = acc;
        }
    }
}

extern "C" void kernel_launch(void* const* d_in, const int* in_sizes, int n_in,
                              void* d_out, int out_size) {
    const float* node_embeds = (const float*)d_in[0];
    const float* bases       = (const float*)d_in[1];
    const float* comp        = (const float*)d_in[2];
    const float* root        = (const float*)d_in[3];
    const float* bias        = (const float*)d_in[4];
    const float* w1          = (const float*)d_in[5];
    const float* b1          = (const float*)d_in[6];
    const float* w2          = (const float*)d_in[7];
    const float* b2          = (const float*)d_in[8];
    const float* wp          = (const float*)d_in[9];
    const float* bp          = (const float*)d_in[10];
    const int*   edge_index  = (const int*)d_in[11];
    const int*   edge_type   = (const int*)d_in[12];
    const int*   entity_ids  = (const int*)d_in[13];
    float* out = (float*)d_out;

    const int smem_bytes = (TILE * DD + TILE * NB * DD + N_REL * NB + TILE * N_REL +
                            TILE * DD + TILE * 64) * 4 + TILE * 4;
    cudaFuncSetAttribute(k_final, cudaFuncAttributeMaxDynamicSharedMemorySize, smem_bytes);

    k_init0<<<(N_ENTITY + 255) / 256, 256>>>();
    k_scatter<<<(N_POS + 255) / 256, 256>>>(entity_ids);
    k_filter<<<(NEDGE / 4 + 255) / 256, 256>>>(edge_index, edge_type);
    k_zero<<<64, 256>>>();
    k_accum<<<1024, 128>>>(node_embeds);
    k_final<<<N_POS / TILE, 512, smem_bytes>>>(node_embeds, bases, comp, root, bias,
                                               w1, b1, w2, b2, wp, bp,
                                               entity_ids, out);
    (void)in_sizes; (void)n_in; (void)out_size;
}

// round 5
// speedup vs baseline: 1.4231x; 1.4231x over previous
#include <cuda_runtime.h>

#define N_ENTITY 100000
#define DD 128
#define HIDSZ 256
#define N_REL 48
#define NB 8
#define NEDGE 1000000
#define N_POS 1024
#define CAP (1 << 17)
#define ZMAX (N_POS * N_REL)
#define TILE 8
#define NCHUNK 36          // (1 root + 8 bases) * 128 rows / 32 rows per chunk
#define CROWS 32           // rows per staged chunk
#define WBUF_F (CROWS * DD)  // 4096 floats per buffer

// ---- device scratch (no allocation allowed) ----
__device__ int   g_map[N_ENTITY];
__device__ int   g_deg[N_POS * N_REL];
__device__ float g_s[N_POS * N_REL * DD];
__device__ int4  g_ce[CAP];
__device__ int   g_cnt;
__device__ int   g_zlist[ZMAX];
__device__ int   g_zcnt;

__global__ void k_init0() {
    int i = blockIdx.x * blockDim.x + threadIdx.x;
    if (i < N_ENTITY) g_map[i] = 0x7fffffff;
    if (i < N_POS * N_REL) g_deg[i] = 0;
    if (i == 0) { g_cnt = 0; g_zcnt = 0; }
}

__global__ void k_scatter(const int* __restrict__ ids) {
    int i = blockIdx.x * blockDim.x + threadIdx.x;
    if (i < N_POS) atomicMin(&g_map[ids[i]], i);
}

__global__ void k_filter(const int* __restrict__ ei, const int* __restrict__ et) {
    int t = blockIdx.x * blockDim.x + threadIdx.x;
    if (t * 4 >= NEDGE) return;
    int4 dst4 = reinterpret_cast<const int4*>(ei + NEDGE)[t];
    int ds[4] = {dst4.x, dst4.y, dst4.z, dst4.w};
#pragma unroll
    for (int q = 0; q < 4; ++q) {
        int e = t * 4 + q;
        int slot = g_map[ds[q]];
        if (slot < N_POS) {
            int rel = __ldg(&et[e]);
            int row = slot * N_REL + rel;
            int old = atomicAdd(&g_deg[row], 1);
            if (old == 1) {
                int zp = atomicAdd(&g_zcnt, 1);
                if (zp < ZMAX) g_zlist[zp] = row;
            }
            int p = atomicAdd(&g_cnt, 1);
            if (p < CAP) g_ce[p] = make_int4(__ldg(&ei[e]), slot, rel, 0);
        }
    }
}

__global__ void k_zero() {
    int w = (blockIdx.x * blockDim.x + threadIdx.x) >> 5;
    int lane = threadIdx.x & 31;
    int nw = (gridDim.x * blockDim.x) >> 5;
    int n = min(g_zcnt, ZMAX);
    float4 z = make_float4(0.f, 0.f, 0.f, 0.f);
    for (int i = w; i < n; i += nw) {
        int row = g_zlist[i];
        reinterpret_cast<float4*>(g_s + (size_t)row * DD)[lane] = z;
    }
}

__global__ void k_accum(const float* __restrict__ x) {
    int warp = (blockIdx.x * blockDim.x + threadIdx.x) >> 5;
    int lane = threadIdx.x & 31;
    int nwarp = (gridDim.x * blockDim.x) >> 5;
    int cnt = min(g_cnt, CAP);
    for (int i = warp; i < cnt; i += nwarp) {
        int4 ce = g_ce[i];
        int row = ce.y * N_REL + ce.z;
        int dg = g_deg[row];
        float4 xv = reinterpret_cast<const float4*>(x + (long)ce.x * DD)[lane];
        float* sp = &g_s[(size_t)row * DD + lane * 4];
        if (dg == 1) {
            *reinterpret_cast<float4*>(sp) = xv;
        } else {
            atomicAdd(sp + 0, xv.x);
            atomicAdd(sp + 1, xv.y);
            atomicAdd(sp + 2, xv.z);
            atomicAdd(sp + 3, xv.w);
        }
    }
}

// ---- K4: fused per-position pipeline, smem-staged weights ----
// 256 threads = 2 groups of 128; TILE=8 positions (4 per group).
__global__ __launch_bounds__(256)
void k_final(const float* __restrict__ x, const float* __restrict__ bases,
             const float* __restrict__ comp, const float* __restrict__ root,
             const float* __restrict__ bias,
             const float* __restrict__ w1, const float* __restrict__ b1,
             const float* __restrict__ w2, const float* __restrict__ b2,
             const float* __restrict__ wp, const float* __restrict__ bp,
             const int* __restrict__ ids, float* __restrict__ out) {
    extern __shared__ float sm[];
    float* wbuf  = sm;                        // 2 * 4096 floats (32 KB)
    float* xs    = wbuf + 2 * WBUF_F;         // 1024
    float* vv    = xs + TILE * DD;            // 8192
    float* compS = vv + TILE * NB * DD;       // 384
    float* normS = compS + N_REL * NB;        // 384
    float* hb    = normS + TILE * N_REL;      // 1024
    float* zb    = hb + TILE * DD;            // 512
    int*  canon  = (int*)(zb + TILE * 64);    // 8 ints

    const int tid = threadIdx.x;
    const int g   = tid >> 7;     // 0 or 1
    const int d   = tid & 127;
    const int pbase = blockIdx.x * TILE;

    if (tid < TILE) canon[tid] = g_map[ids[pbase + tid]];
    for (int i = tid; i < TILE * DD; i += 256) {
        int p = i >> 7;
        xs[i] = x[(long)ids[pbase + p] * DD + (i & 127)];
    }
    for (int i = tid; i < N_REL * NB; i += 256) compS[i] = comp[i];   // FIX: loop, 384 > 256
    __syncthreads();
    for (int i = tid; i < TILE * N_REL; i += 256) {                   // FIX: loop, 384 > 256
        int p = i / N_REL, r = i % N_REL;
        int dg = g_deg[canon[p] * N_REL + r];
        normS[i] = dg > 0 ? 1.0f / (float)dg : 0.0f;
    }

    // preload weight chunk 0 (root rows 0..31) into registers
    float4 stage[4];
    {
        const float4* src = reinterpret_cast<const float4*>(root);
#pragma unroll
        for (int t = 0; t < 4; ++t) stage[t] = src[tid + t * 256];
    }
    __syncthreads();

    // ---- phase 2: vv[p][k][d] = sum_{r: deg>0} norm*s*comp ----
#pragma unroll
    for (int p = 0; p < 4; ++p) {
        int pp = g * 4 + p;
        const float* srow = &g_s[(size_t)canon[pp] * N_REL * DD + d];
        float acc[NB];
#pragma unroll
        for (int k = 0; k < NB; ++k) acc[k] = 0.0f;
        for (int r = 0; r < N_REL; ++r) {
            float nm = normS[pp * N_REL + r];
            if (nm != 0.0f) {
                float sv = srow[r * DD] * nm;
#pragma unroll
                for (int k = 0; k < NB; ++k) acc[k] += sv * compS[r * NB + k];
            }
        }
#pragma unroll
        for (int k = 0; k < NB; ++k) vv[(pp * NB + k) * DD + d] = acc[k];
    }
    // store preloaded chunk 0
    {
        float4* dst = reinterpret_cast<float4*>(wbuf);
#pragma unroll
        for (int t = 0; t < 4; ++t) dst[tid + t * 256] = stage[t];
    }
    __syncthreads();  // vv ready + chunk 0 staged

    // ---- phase 3: hb = bias + xs@root + sum_k vv_k@B_k + xs (residual) ----
    {
        float acc0 = bias[d], acc1 = acc0, acc2 = acc0, acc3 = acc0;
        const int pp0 = g * 4;
        int buf = 0;
        for (int cc = 0; cc < NCHUNK; ++cc) {
            // issue loads for next chunk
            if (cc + 1 < NCHUNK) {
                int m = (cc + 1) >> 2;
                int j0 = ((cc + 1) & 3) * CROWS;
                const float* wsrc = (m == 0) ? (root + j0 * DD)
                                             : (bases + ((size_t)(m - 1) * DD + j0) * DD);
                const float4* src = reinterpret_cast<const float4*>(wsrc);
#pragma unroll
                for (int t = 0; t < 4; ++t) stage[t] = src[tid + t * 256];
            }
            // compute from current buffer
            {
                int m = cc >> 2;
                int j0 = (cc & 3) * CROWS;
                const float* a0 = (m == 0) ? (xs + pp0 * DD + j0)
                                           : (vv + (pp0 * NB + (m - 1)) * DD + j0);
                const float* a1 = (m == 0) ? (xs + (pp0 + 1) * DD + j0)
                                           : (vv + ((pp0 + 1) * NB + (m - 1)) * DD + j0);
                const float* a2 = (m == 0) ? (xs + (pp0 + 2) * DD + j0)
                                           : (vv + ((pp0 + 2) * NB + (m - 1)) * DD + j0);
                const float* a3 = (m == 0) ? (xs + (pp0 + 3) * DD + j0)
                                           : (vv + ((pp0 + 3) * NB + (m - 1)) * DD + j0);
                const float* wrow = wbuf + buf * WBUF_F + d;
#pragma unroll
                for (int jj4 = 0; jj4 < CROWS / 4; ++jj4) {
                    float w0 = wrow[(jj4 * 4 + 0) * DD];
                    float w1v = wrow[(jj4 * 4 + 1) * DD];
                    float w2v = wrow[(jj4 * 4 + 2) * DD];
                    float w3v = wrow[(jj4 * 4 + 3) * DD];
                    float4 v0 = reinterpret_cast<const float4*>(a0)[jj4];
                    float4 v1 = reinterpret_cast<const float4*>(a1)[jj4];
                    float4 v2 = reinterpret_cast<const float4*>(a2)[jj4];
                    float4 v3 = reinterpret_cast<const float4*>(a3)[jj4];
                    acc0 += v0.x * w0 + v0.y * w1v + v0.z * w2v + v0.w * w3v;
                    acc1 += v1.x * w0 + v1.y * w1v + v1.z * w2v + v1.w * w3v;
                    acc2 += v2.x * w0 + v2.y * w1v + v2.z * w2v + v2.w * w3v;
                    acc3 += v3.x * w0 + v3.y * w1v + v3.z * w2v + v3.w * w3v;
                }
            }
            // store next chunk into the other buffer
            if (cc + 1 < NCHUNK) {
                float4* dst = reinterpret_cast<float4*>(wbuf + (buf ^ 1) * WBUF_F);
#pragma unroll
                for (int t = 0; t < 4; ++t) dst[tid + t * 256] = stage[t];
                buf ^= 1;
            }
            __syncthreads();
        }
        hb[pp0 * DD + d]       = acc0 + xs[pp0 * DD + d];
        hb[(pp0 + 1) * DD + d] = acc1 + xs[(pp0 + 1) * DD + d];
        hb[(pp0 + 2) * DD + d] = acc2 + xs[(pp0 + 2) * DD + d];
        hb[(pp0 + 3) * DD + d] = acc3 + xs[(pp0 + 3) * DD + d];
    }
    __syncthreads();

    // ---- stage w1 (128x64 = 8192 floats) into wbuf ----
    {
        const float4* src = reinterpret_cast<const float4*>(w1);
        float4* dst = reinterpret_cast<float4*>(wbuf);
#pragma unroll
        for (int t = 0; t < 8; ++t) dst[tid + t * 256] = src[tid + t * 256];
    }
    __syncthreads();

    // ---- phase 5: zb[p][c] = relu(hb[p] @ w1 + b1) ----
    {
        int c = tid & 63, ph = tid >> 6;   // ph: 0..3 -> positions 2ph, 2ph+1
        int p0 = ph * 2;
        float acc0 = b1[c], acc1 = acc0;
        const float* wcol = wbuf + c;
        const float4* h0 = reinterpret_cast<const float4*>(hb + p0 * DD);
        const float4* h1 = reinterpret_cast<const float4*>(hb + (p0 + 1) * DD);
#pragma unroll 4
        for (int j4 = 0; j4 < DD / 4; ++j4) {
            float w0 = wcol[(j4 * 4 + 0) * 64];
            float w1v = wcol[(j4 * 4 + 1) * 64];
            float w2v = wcol[(j4 * 4 + 2) * 64];
            float w3v = wcol[(j4 * 4 + 3) * 64];
            float4 a = h0[j4], b = h1[j4];
            acc0 += a.x * w0 + a.y * w1v + a.z * w2v + a.w * w3v;
            acc1 += b.x * w0 + b.y * w1v + b.z * w2v + b.w * w3v;
        }
        zb[p0 * 64 + c] = fmaxf(acc0, 0.0f);
        zb[(p0 + 1) * 64 + c] = fmaxf(acc1, 0.0f);
    }
    __syncthreads();

    // ---- stage w2 (64x128 = 8192 floats) into wbuf ----
    {
        const float4* src = reinterpret_cast<const float4*>(w2);
        float4* dst = reinterpret_cast<float4*>(wbuf);
#pragma unroll
        for (int t = 0; t < 8; ++t) dst[tid + t * 256] = src[tid + t * 256];
    }
    __syncthreads();

    // ---- phase 6: hb[p][dd] += zb[p] @ w2 + b2 ----
    {
        int dd2 = tid & 127, t2 = tid >> 7;  // t2: 0/1 -> positions 4t2..4t2+3
        int p0 = t2 * 4;
        float acc[4];
#pragma unroll
        for (int p = 0; p < 4; ++p) acc[p] = b2[dd2] + hb[(p0 + p) * DD + dd2];
        const float* wcol = wbuf + dd2;
#pragma unroll 4
        for (int c4 = 0; c4 < 16; ++c4) {
            float w0 = wcol[(c4 * 4 + 0) * DD];
            float w1v = wcol[(c4 * 4 + 1) * DD];
            float w2v = wcol[(c4 * 4 + 2) * DD];
            float w3v = wcol[(c4 * 4 + 3) * DD];
#pragma unroll
            for (int p = 0; p < 4; ++p) {
                float4 z = reinterpret_cast<const float4*>(zb + (p0 + p) * 64)[c4];
                acc[p] += z.x * w0 + z.y * w1v + z.z * w2v + z.w * w3v;
            }
        }
        __syncthreads();
#pragma unroll
        for (int p = 0; p < 4; ++p) hb[(p0 + p) * DD + dd2] = acc[p];
    }
    __syncthreads();

    // ---- phase 7: out[pos][o] = hb[p] @ wp + bp  (thread owns o, 8 accs) ----
    {
        int o = tid;  // 0..255
        float acc[8];
        float b = bp[o];
#pragma unroll
        for (int p = 0; p < 8; ++p) acc[p] = b;
        const float* wcol = wp + o;
#pragma unroll 2
        for (int j4 = 0; j4 < DD / 4; ++j4) {
            float w0 = wcol[(size_t)(j4 * 4 + 0) * HIDSZ];
            float w1v = wcol[(size_t)(j4 * 4 + 1) * HIDSZ];
            float w2v = wcol[(size_t)(j4 * 4 + 2) * HIDSZ];
            float w3v = wcol[(size_t)(j4 * 4 + 3) * HIDSZ];
#pragma unroll
            for (int p = 0; p < 8; ++p) {
                float4 h = reinterpret_cast<const float4*>(hb + p * DD)[j4];
                acc[p] += h.x * w0 + h.y * w1v + h.z * w2v + h.w * w3v;
            }
        }
#pragma unroll
        for (int p = 0; p < 8; ++p)
            out[((long)(pbase + p)) * HIDSZ + o] = acc[p];
    }
}

extern "C" void kernel_launch(void* const* d_in, const int* in_sizes, int n_in,
                              void* d_out, int out_size) {
    const float* node_embeds = (const float*)d_in[0];
    const float* bases       = (const float*)d_in[1];
    const float* comp        = (const float*)d_in[2];
    const float* root        = (const float*)d_in[3];
    const float* bias        = (const float*)d_in[4];
    const float* w1          = (const float*)d_in[5];
    const float* b1          = (const float*)d_in[6];
    const float* w2          = (const float*)d_in[7];
    const float* b2          = (const float*)d_in[8];
    const float* wp          = (const float*)d_in[9];
    const float* bp          = (const float*)d_in[10];
    const int*   edge_index  = (const int*)d_in[11];
    const int*   edge_type   = (const int*)d_in[12];
    const int*   entity_ids  = (const int*)d_in[13];
    float* out = (float*)d_out;

    const int smem_bytes = (2 * WBUF_F + TILE * DD + TILE * NB * DD + N_REL * NB +
                            TILE * N_REL + TILE * DD + TILE * 64) * 4 + TILE * 4;
    cudaFuncSetAttribute(k_final, cudaFuncAttributeMaxDynamicSharedMemorySize, smem_bytes);

    k_init0<<<(N_ENTITY + 255) / 256, 256>>>();
    k_scatter<<<(N_POS + 255) / 256, 256>>>(entity_ids);
    k_filter<<<(NEDGE / 4 + 255) / 256, 256>>>(edge_index, edge_type);
    k_zero<<<256, 128>>>();
    k_accum<<<1024, 128>>>(node_embeds);
    k_final<<<N_POS / TILE, 256, smem_bytes>>>(node_embeds, bases, comp, root, bias,
                                               w1, b1, w2, b2, wp, bp,
                                               entity_ids, out);
    (void)in_sizes; (void)n_in; (void)out_size;
}